// round 10
// baseline (speedup 1.0000x reference)
#include <cuda_runtime.h>
#include <cstdint>

// ---------------------------------------------------------------------------
// WunschLineMatcher — full pipeline on GB300 (sm_103a)
//
// Stages:
//  T) transpose desc [c][y][x] -> [y][x][c]  (coalesced bilinear gathers later)
//  A) sample line points + bilinear-sample + L2-normalize 128-d descriptors
//  B) fused 5120x5120x128 fp32 GEMM (packed fma.rn.f32x2) with per-pair-block
//     (10x10) masked max/mean epilogue -> line_scores[512][512] only
//  C) top-10 per row (dir0) / per col (dir1) with argsort-stable tie handling
//  D) recompute 10x10 blocks for top-10 candidates, run Needleman-Wunsch
//     (forward + flipped), argmax -> per-direction matches
//  E) mutual-consistency check -> FLOAT32 output (harness __output__ dtype:
//     int32 -1 bit pattern is float NaN -> must emit floats)
// ---------------------------------------------------------------------------

#define NLINES 512
#define SAMP   10
#define DCH    128
#define HC     128
#define WC     128
#define NPTS   (NLINES * SAMP)   // 5120

// scratch (static __device__ — no allocations allowed).
// __align__(16): k_linescore uses 128-bit global loads on g_dsc and 64-bit
// shared loads on As/Bs.
__device__ __align__(16) float g_dT[2][HC * WC * DCH];  // [set][(y*128+x)*128+c]
__device__ __align__(16) float g_dsc[2][NPTS * DCH];    // [set][point*128 + k]
__device__ int   g_valid[2][NPTS];
__device__ float g_ls[NLINES * NLINES];       // line_scores[i_set0][j_set1]
__device__ int   g_topk[2][NLINES * 10];      // ascending order (slot 9 = best)
__device__ int   g_match[2][NLINES];

// ---------------------------------------------------------------------------
// packed fp32x2 helpers
// ---------------------------------------------------------------------------
__device__ __forceinline__ void ffma2(unsigned long long& d,
                                      unsigned long long a,
                                      unsigned long long b) {
    asm("fma.rn.f32x2 %0, %1, %2, %0;" : "+l"(d) : "l"(a), "l"(b));
}
__device__ __forceinline__ unsigned long long pack2(float x) {
    unsigned long long r;
    asm("mov.b64 %0, {%1, %1};" : "=l"(r) : "f"(x));
    return r;
}
__device__ __forceinline__ void unpack2(unsigned long long v, float& lo, float& hi) {
    asm("mov.b64 {%0, %1}, %2;" : "=f"(lo), "=f"(hi) : "l"(v));
}

// ---------------------------------------------------------------------------
// T: transpose [c][y*x] (128 x 16384) -> [y*x][c]
// ---------------------------------------------------------------------------
__global__ void k_transpose(const float* __restrict__ d0,
                            const float* __restrict__ d1) {
    const float* src = blockIdx.z ? d1 : d0;
    float* dst = g_dT[blockIdx.z];
    __shared__ float tile[32][33];
    int p0 = blockIdx.x * 32;   // yx tile base (16384 / 32 = 512 blocks)
    int c0 = blockIdx.y * 32;   // channel tile base (128 / 32 = 4 blocks)
    int tx = threadIdx.x, ty = threadIdx.y;
#pragma unroll
    for (int i = 0; i < 4; i++)
        tile[ty + 8 * i][tx] = src[(size_t)(c0 + ty + 8 * i) * 16384 + p0 + tx];
    __syncthreads();
#pragma unroll
    for (int i = 0; i < 4; i++)
        dst[(size_t)(p0 + ty + 8 * i) * 128 + c0 + tx] = tile[tx][ty + 8 * i];
}

// ---------------------------------------------------------------------------
// A: sample + bilinear + normalize.  one block (128 thr) per point.
// replicates reference fp32 op-by-op (no fma contraction, IEEE div/sqrt).
// ---------------------------------------------------------------------------
__global__ void k_sample(const float* __restrict__ seg0,
                         const float* __restrict__ seg1) {
    int b = blockIdx.x;                 // 0 .. 10239
    int set = (b >= NPTS) ? 1 : 0;
    int pid = b - set * NPTS;
    int line = pid / SAMP;
    int t    = pid - line * SAMP;
    const float* seg = set ? seg1 : seg0;
    const float* dT  = g_dT[set];

    float a0 = seg[line * 4 + 0], a1 = seg[line * 4 + 1];
    float b0 = seg[line * 4 + 2], b1 = seg[line * 4 + 3];
    float e0 = __fsub_rn(a0, b0), e1 = __fsub_rn(a1, b1);
    float len = __fsqrt_rn(__fadd_rn(__fmul_rn(e0, e0), __fmul_rn(e1, e1)));
    float ns  = fminf(fmaxf(floorf(__fmul_rn(len, 0.125f)), 2.0f), 10.0f);
    float tf  = (float)t;
    int valid = (tf < ns) ? 1 : 0;
    float iv0 = __fdiv_rn(__fsub_rn(b0, a0), __fsub_rn(ns, 1.0f));
    float iv1 = __fdiv_rn(__fsub_rn(b1, a1), __fsub_rn(ns, 1.0f));
    float py  = __fadd_rn(a0, __fmul_rn(tf, iv0));   // coord0 -> "y" (H axis)
    float px  = __fadd_rn(a1, __fmul_rn(tf, iv1));   // coord1 -> "x" (W axis)
    if (!valid) { py = 0.0f; px = 0.0f; }

    // grid coords (H = W = 512, Hc = Wc = 128)
    float gx = __fsub_rn(__fdiv_rn(__fmul_rn(2.0f, px), 511.0f), 1.0f);
    float gy = __fsub_rn(__fdiv_rn(__fmul_rn(2.0f, py), 511.0f), 1.0f);
    float ix = __fmul_rn(__fsub_rn(__fmul_rn(__fadd_rn(gx, 1.0f), 128.0f), 1.0f), 0.5f);
    float iy = __fmul_rn(__fsub_rn(__fmul_rn(__fadd_rn(gy, 1.0f), 128.0f), 1.0f), 0.5f);
    float x0f = floorf(ix), y0f = floorf(iy);
    float wx = __fsub_rn(ix, x0f), wy = __fsub_rn(iy, y0f);
    float owx = __fsub_rn(1.0f, wx), owy = __fsub_rn(1.0f, wy);
    int x0 = (int)x0f, y0 = (int)y0f;

    int c = threadIdx.x;
    auto G = [&](int yy, int xx) -> float {
        bool inb = (xx >= 0) & (xx < WC) & (yy >= 0) & (yy < HC);
        int yc = min(max(yy, 0), HC - 1);
        int xc = min(max(xx, 0), WC - 1);
        float v = dT[(size_t)(yc * WC + xc) * DCH + c];
        return inb ? v : 0.0f;
    };
    float t1 = __fmul_rn(__fmul_rn(G(y0, x0), owy), owx);
    float t2 = __fmul_rn(__fmul_rn(G(y0, x0 + 1), owy), wx);
    float t3 = __fmul_rn(__fmul_rn(G(y0 + 1, x0), wy), owx);
    float t4 = __fmul_rn(__fmul_rn(G(y0 + 1, x0 + 1), wy), wx);
    float v = __fadd_rn(__fadd_rn(__fadd_rn(t1, t2), t3), t4);

    // block-wide sum of squares
    float sq = __fmul_rn(v, v);
#pragma unroll
    for (int o = 16; o > 0; o >>= 1)
        sq = __fadd_rn(sq, __shfl_xor_sync(0xffffffffu, sq, o));
    __shared__ float wsum[4];
    __shared__ float s_nrm;
    int wid = threadIdx.x >> 5;
    if ((threadIdx.x & 31) == 0) wsum[wid] = sq;
    __syncthreads();
    if (threadIdx.x == 0) {
        float s = __fadd_rn(__fadd_rn(__fadd_rn(wsum[0], wsum[1]), wsum[2]), wsum[3]);
        s_nrm = fmaxf(__fsqrt_rn(s), 1e-12f);
    }
    __syncthreads();
    g_dsc[set][(size_t)pid * DCH + c] = __fdiv_rn(v, s_nrm);
    if (c == 0) g_valid[set][pid] = valid;
}

// ---------------------------------------------------------------------------
// B: fused line_scores.  block = 8x8 line pairs (80x80 C tile), 64 threads,
// each thread owns one full 10x10 pair block.  K chunked 2x64 in smem.
// ---------------------------------------------------------------------------
__global__ __launch_bounds__(64)
void k_linescore() {
    __shared__ __align__(16) float As[64 * 80];   // [k][row] rows = set0 pts
    __shared__ __align__(16) float Bs[64 * 80];   // [k][col] cols = set1 pts
    __shared__ int v1s[80], v2s[80];

    int tid = threadIdx.x;
    int tx = tid & 7;          // j-line sub-index
    int ty = tid >> 3;         // i-line sub-index
    int rowA0 = blockIdx.y * 80;
    int rowB0 = blockIdx.x * 80;

    for (int i = tid; i < 80; i += 64) {
        v1s[i] = g_valid[0][rowA0 + i];
        v2s[i] = g_valid[1][rowB0 + i];
    }

    unsigned long long acc[10][5];
#pragma unroll
    for (int r = 0; r < 10; r++)
#pragma unroll
        for (int c = 0; c < 5; c++) acc[r][c] = 0ull;

    for (int kc = 0; kc < 128; kc += 64) {
        // cooperative load: 80 rows x 64 k (float4 = 16 f4/row)
#pragma unroll
        for (int l = 0; l < 20; l++) {
            int idx = tid + (l << 6);          // 0..1279
            int row = idx >> 4;
            int q   = idx & 15;
            float4 va = *reinterpret_cast<const float4*>(
                &g_dsc[0][(size_t)(rowA0 + row) * 128 + kc + q * 4]);
            float4 vb = *reinterpret_cast<const float4*>(
                &g_dsc[1][(size_t)(rowB0 + row) * 128 + kc + q * 4]);
            int kb = q * 4;
            As[(kb + 0) * 80 + row] = va.x;
            As[(kb + 1) * 80 + row] = va.y;
            As[(kb + 2) * 80 + row] = va.z;
            As[(kb + 3) * 80 + row] = va.w;
            Bs[(kb + 0) * 80 + row] = vb.x;
            Bs[(kb + 1) * 80 + row] = vb.y;
            Bs[(kb + 2) * 80 + row] = vb.z;
            Bs[(kb + 3) * 80 + row] = vb.w;
        }
        __syncthreads();

#pragma unroll 8
        for (int kk = 0; kk < 64; kk++) {
            const float* ap = &As[kk * 80 + ty * 10];
            const unsigned long long* bp =
                reinterpret_cast<const unsigned long long*>(&Bs[kk * 80 + tx * 10]);
            unsigned long long bv[5];
#pragma unroll
            for (int c = 0; c < 5; c++) bv[c] = bp[c];
#pragma unroll
            for (int r = 0; r < 10; r++) {
                unsigned long long a2 = pack2(ap[r]);
#pragma unroll
                for (int c = 0; c < 5; c++) ffma2(acc[r][c], a2, bv[c]);
            }
        }
        __syncthreads();
    }

    // epilogue: unpack, mask, 10x10 max/mean reductions
    float sc[10][10];
#pragma unroll
    for (int r = 0; r < 10; r++)
#pragma unroll
        for (int c = 0; c < 5; c++)
            unpack2(acc[r][c], sc[r][2 * c], sc[r][2 * c + 1]);

    int vr[10], vc[10];
#pragma unroll
    for (int s = 0; s < 10; s++) { vr[s] = v1s[ty * 10 + s]; vc[s] = v2s[tx * 10 + s]; }
#pragma unroll
    for (int r = 0; r < 10; r++)
#pragma unroll
        for (int c = 0; c < 10; c++)
            if (!(vr[r] && vc[c])) sc[r][c] = -1.0f;

    float sum1 = 0.0f; int c1 = 0;
#pragma unroll
    for (int r = 0; r < 10; r++) {
        float m = sc[r][0];
#pragma unroll
        for (int c = 1; c < 10; c++) m = fmaxf(m, sc[r][c]);
        if (m != -1.0f) { sum1 = __fadd_rn(sum1, m); c1++; }
    }
    float sum2 = 0.0f; int c2 = 0;
#pragma unroll
    for (int c = 0; c < 10; c++) {
        float m = sc[0][c];
#pragma unroll
        for (int r = 1; r < 10; r++) m = fmaxf(m, sc[r][c]);
        if (m != -1.0f) { sum2 = __fadd_rn(sum2, m); c2++; }
    }
    float m1 = __fdiv_rn(sum1, (float)c1);
    float m2 = __fdiv_rn(sum2, (float)c2);
    int i_line = blockIdx.y * 8 + ty;
    int j_line = blockIdx.x * 8 + tx;
    g_ls[i_line * NLINES + j_line] = __fmul_rn(__fadd_rn(m1, m2), 0.5f);
}

// ---------------------------------------------------------------------------
// C: top-10 per row (dir0) / per column (dir1) of line_scores.
// argsort(stable, ascending)[-10:] semantics: selection ties -> larger index;
// stored ascending (slot 9 = best).
// ---------------------------------------------------------------------------
__global__ void k_topk() {
    int blk = blockIdx.x;
    int dir = blk >> 9;
    int i   = blk & 511;
    int tid = threadIdx.x;    // 512 threads
    __shared__ float v[512];
    __shared__ float rv[512];
    __shared__ int   ri[512];
    v[tid] = (dir == 0) ? g_ls[i * NLINES + tid] : g_ls[tid * NLINES + i];
    __syncthreads();
    for (int it = 0; it < 10; it++) {
        rv[tid] = v[tid]; ri[tid] = tid;
        __syncthreads();
        for (int s = 256; s > 0; s >>= 1) {
            if (tid < s) {
                float vo = rv[tid + s]; int io = ri[tid + s];
                if (vo > rv[tid] || (vo == rv[tid] && io > ri[tid])) {
                    rv[tid] = vo; ri[tid] = io;
                }
            }
            __syncthreads();
        }
        if (tid == 0) {
            g_topk[dir][i * 10 + (9 - it)] = ri[0];
            v[ri[0]] = -3.0e38f;
        }
        __syncthreads();
    }
}

// ---------------------------------------------------------------------------
// D: per (dir, line): recompute 10 candidate 10x10 blocks, run NW fwd+flip,
// argmax (first occurrence), match = topk[best % 10].
// ---------------------------------------------------------------------------
__global__ void k_match() {
    int blk = blockIdx.x;
    int dir = blk >> 9;
    int line = blk & 511;
    int qset = dir, cset = 1 - dir;
    int tid = threadIdx.x;    // 128 threads

    __shared__ float qd[SAMP * DCH];   // query descriptors (5KB)
    __shared__ int   qv[SAMP];
    __shared__ int   cands[10];
    __shared__ float sc[10 * 10 * 10]; // [cand][sq][sc]
    __shared__ float nw[20];

    for (int t = tid; t < SAMP * DCH; t += 128)
        qd[t] = g_dsc[qset][(size_t)(line * SAMP) * DCH + t];
    if (tid < SAMP) qv[tid] = g_valid[qset][line * SAMP + tid];
    if (tid < 10)  cands[tid] = g_topk[dir][line * 10 + tid];
    __syncthreads();

    for (int idx = tid; idx < 1000; idx += 128) {
        int c   = idx / 100;
        int rem = idx - c * 100;
        int sq  = rem / 10;
        int s2  = rem - sq * 10;
        int cand = cands[c];
        const float* cd = &g_dsc[cset][(size_t)(cand * SAMP + s2) * DCH];
        const float* qp = &qd[sq * DCH];
        float sum = 0.0f;
#pragma unroll 8
        for (int k = 0; k < DCH; k++) sum = __fmaf_rn(qp[k], cd[k], sum);
        int cvalid = g_valid[cset][cand * SAMP + s2];
        sc[idx] = (qv[sq] && cvalid) ? sum : -1.0f;
    }
    __syncthreads();

    if (tid < 20) {
        int c = tid % 10;
        int flip = tid / 10;
        float prev[11];
#pragma unroll
        for (int j = 0; j < 11; j++) prev[j] = 0.0f;
#pragma unroll
        for (int r = 0; r < 10; r++) {
            float diag = prev[0];
            float run = -3.0e38f;
#pragma unroll
            for (int cc = 0; cc < 10; cc++) {
                int col = flip ? (9 - cc) : cc;
                float sval = __fsub_rn(sc[c * 100 + r * 10 + col], 0.1f);
                float oldn = prev[cc + 1];
                float a = fmaxf(oldn, __fadd_rn(diag, sval));
                run = fmaxf(run, a);
                prev[cc + 1] = fmaxf(run, 0.0f);
                diag = oldn;
            }
        }
        nw[tid] = prev[10];
    }
    __syncthreads();
    if (tid == 0) {
        int best = 0; float bv = nw[0];
        for (int j = 1; j < 20; j++)
            if (nw[j] > bv) { bv = nw[j]; best = j; }
        g_match[dir][line] = cands[best % 10];
    }
}

// ---------------------------------------------------------------------------
// E: mutual consistency -> FLOAT32 output.
// int32 -1 bit pattern (0xFFFFFFFF) is NaN when the harness reads the output
// buffer as float32; emit float values instead.
// ---------------------------------------------------------------------------
__global__ void k_mutual(float* __restrict__ out) {
    int i = threadIdx.x;
    int m = g_match[0][i];
    out[i] = (g_match[1][m] == i) ? (float)m : -1.0f;
}

// ---------------------------------------------------------------------------
extern "C" void kernel_launch(void* const* d_in, const int* in_sizes, int n_in,
                              void* d_out, int out_size) {
    const float* seg1  = (const float*)d_in[0];
    const float* seg2  = (const float*)d_in[1];
    const float* desc1 = (const float*)d_in[2];
    const float* desc2 = (const float*)d_in[3];
    float* out = (float*)d_out;

    k_transpose<<<dim3(512, 4, 2), dim3(32, 8)>>>(desc1, desc2);
    k_sample<<<2 * NPTS, 128>>>(seg1, seg2);
    k_linescore<<<dim3(64, 64), 64>>>();
    k_topk<<<1024, 512>>>();
    k_match<<<1024, 128>>>();
    k_mutual<<<1, 512>>>(out);
}

// round 12
// speedup vs baseline: 1.4749x; 1.4749x over previous
#include <cuda_runtime.h>
#include <cstdint>

// ---------------------------------------------------------------------------
// WunschLineMatcher — full pipeline on GB300 (sm_103a)
//
//  T) transpose desc [c][y][x] -> [y][x][c]
//  A) sample line points + bilinear + L2-normalize (warp per point)
//  B) fused 5120x5120x128 fp32 GEMM (fma.rn.f32x2) + per-pair-block (10x10)
//     masked max/mean epilogue -> line_scores[512][512].
//     A tile row-major (conflict-free), B tile transposed w/ padded stride.
//  C) top-10 per row/col: warp-per-row register top-k (argsort-stable ties)
//  D) NW on recomputed 10x10 candidate blocks (fwd + flipped), argmax
//  E) mutual check -> float32 output (-1 as int bit-pattern would be NaN)
// ---------------------------------------------------------------------------

#define NLINES 512
#define SAMP   10
#define DCH    128
#define HC     128
#define WC     128
#define NPTS   (NLINES * SAMP)   // 5120

#define ASTRIDE 68   // A tile row stride in floats (64 k + 4 pad) -> 272B, 16B-aligned
#define BSTRIDE 82   // B tile k-slice stride in floats (80 cols + 2 pad), even for LDS64

__device__ __align__(16) float g_dT[2][HC * WC * DCH];  // [set][(y*128+x)*128+c]
__device__ __align__(16) float g_dsc[2][NPTS * DCH];    // [set][point*128 + k]
__device__ int   g_valid[2][NPTS];
__device__ float g_ls[NLINES * NLINES];       // line_scores[i_set0][j_set1]
__device__ int   g_topk[2][NLINES * 10];      // ascending (slot 9 = best)
__device__ int   g_match[2][NLINES];

// ---------------------------------------------------------------------------
__device__ __forceinline__ void ffma2(unsigned long long& d,
                                      unsigned long long a,
                                      unsigned long long b) {
    asm("fma.rn.f32x2 %0, %1, %2, %0;" : "+l"(d) : "l"(a), "l"(b));
}
__device__ __forceinline__ unsigned long long pack2(float x) {
    unsigned long long r;
    asm("mov.b64 %0, {%1, %1};" : "=l"(r) : "f"(x));
    return r;
}
__device__ __forceinline__ void unpack2(unsigned long long v, float& lo, float& hi) {
    asm("mov.b64 {%0, %1}, %2;" : "=f"(lo), "=f"(hi) : "l"(v));
}

// ---------------------------------------------------------------------------
// T: transpose [c][y*x] (128 x 16384) -> [y*x][c]
// ---------------------------------------------------------------------------
__global__ void k_transpose(const float* __restrict__ d0,
                            const float* __restrict__ d1) {
    const float* src = blockIdx.z ? d1 : d0;
    float* dst = g_dT[blockIdx.z];
    __shared__ float tile[32][33];
    int p0 = blockIdx.x * 32;
    int c0 = blockIdx.y * 32;
    int tx = threadIdx.x, ty = threadIdx.y;
#pragma unroll
    for (int i = 0; i < 4; i++)
        tile[ty + 8 * i][tx] = src[(size_t)(c0 + ty + 8 * i) * 16384 + p0 + tx];
    __syncthreads();
#pragma unroll
    for (int i = 0; i < 4; i++)
        dst[(size_t)(p0 + ty + 8 * i) * 128 + c0 + tx] = tile[tx][ty + 8 * i];
}

// ---------------------------------------------------------------------------
// A: sample + bilinear + normalize.  one WARP per point (no block syncs).
// fp32 op-by-op identical to reference for the coordinate math.
// ---------------------------------------------------------------------------
__global__ void k_sample(const float* __restrict__ seg0,
                         const float* __restrict__ seg1) {
    int warp = blockIdx.x * (blockDim.x >> 5) + (threadIdx.x >> 5);  // 0..10239
    int lane = threadIdx.x & 31;
    int set = (warp >= NPTS) ? 1 : 0;
    int pid = warp - set * NPTS;
    int line = pid / SAMP;
    int t    = pid - line * SAMP;
    const float* seg = set ? seg1 : seg0;
    const float* dT  = g_dT[set];

    float a0 = seg[line * 4 + 0], a1 = seg[line * 4 + 1];
    float b0 = seg[line * 4 + 2], b1 = seg[line * 4 + 3];
    float e0 = __fsub_rn(a0, b0), e1 = __fsub_rn(a1, b1);
    float len = __fsqrt_rn(__fadd_rn(__fmul_rn(e0, e0), __fmul_rn(e1, e1)));
    float ns  = fminf(fmaxf(floorf(__fmul_rn(len, 0.125f)), 2.0f), 10.0f);
    float tf  = (float)t;
    int valid = (tf < ns) ? 1 : 0;
    float iv0 = __fdiv_rn(__fsub_rn(b0, a0), __fsub_rn(ns, 1.0f));
    float iv1 = __fdiv_rn(__fsub_rn(b1, a1), __fsub_rn(ns, 1.0f));
    float py  = __fadd_rn(a0, __fmul_rn(tf, iv0));
    float px  = __fadd_rn(a1, __fmul_rn(tf, iv1));
    if (!valid) { py = 0.0f; px = 0.0f; }

    float gx = __fsub_rn(__fdiv_rn(__fmul_rn(2.0f, px), 511.0f), 1.0f);
    float gy = __fsub_rn(__fdiv_rn(__fmul_rn(2.0f, py), 511.0f), 1.0f);
    float ix = __fmul_rn(__fsub_rn(__fmul_rn(__fadd_rn(gx, 1.0f), 128.0f), 1.0f), 0.5f);
    float iy = __fmul_rn(__fsub_rn(__fmul_rn(__fadd_rn(gy, 1.0f), 128.0f), 1.0f), 0.5f);
    float x0f = floorf(ix), y0f = floorf(iy);
    float wx = __fsub_rn(ix, x0f), wy = __fsub_rn(iy, y0f);
    float owx = __fsub_rn(1.0f, wx), owy = __fsub_rn(1.0f, wy);
    int x0 = (int)x0f, y0 = (int)y0f;

    int c4 = lane * 4;
    auto G4 = [&](int yy, int xx) -> float4 {
        bool inb = (xx >= 0) & (xx < WC) & (yy >= 0) & (yy < HC);
        int yc = min(max(yy, 0), HC - 1);
        int xc = min(max(xx, 0), WC - 1);
        float4 v = *reinterpret_cast<const float4*>(
            &dT[(size_t)(yc * WC + xc) * DCH + c4]);
        if (!inb) { v.x = 0.f; v.y = 0.f; v.z = 0.f; v.w = 0.f; }
        return v;
    };
    float4 p00 = G4(y0, x0), p01 = G4(y0, x0 + 1);
    float4 p10 = G4(y0 + 1, x0), p11 = G4(y0 + 1, x0 + 1);

    auto bil = [&](float g1, float g2, float g3, float g4) -> float {
        float t1 = __fmul_rn(__fmul_rn(g1, owy), owx);
        float t2 = __fmul_rn(__fmul_rn(g2, owy), wx);
        float t3 = __fmul_rn(__fmul_rn(g3, wy), owx);
        float t4 = __fmul_rn(__fmul_rn(g4, wy), wx);
        return __fadd_rn(__fadd_rn(__fadd_rn(t1, t2), t3), t4);
    };
    float v0 = bil(p00.x, p01.x, p10.x, p11.x);
    float v1 = bil(p00.y, p01.y, p10.y, p11.y);
    float v2 = bil(p00.z, p01.z, p10.z, p11.z);
    float v3 = bil(p00.w, p01.w, p10.w, p11.w);

    float sq = __fadd_rn(__fadd_rn(__fadd_rn(__fmul_rn(v0, v0), __fmul_rn(v1, v1)),
                                   __fmul_rn(v2, v2)), __fmul_rn(v3, v3));
#pragma unroll
    for (int o = 16; o > 0; o >>= 1)
        sq = __fadd_rn(sq, __shfl_xor_sync(0xffffffffu, sq, o));
    float nrm = fmaxf(__fsqrt_rn(sq), 1e-12f);

    float4 outv;
    outv.x = __fdiv_rn(v0, nrm);
    outv.y = __fdiv_rn(v1, nrm);
    outv.z = __fdiv_rn(v2, nrm);
    outv.w = __fdiv_rn(v3, nrm);
    *reinterpret_cast<float4*>(&g_dsc[set][(size_t)pid * DCH + c4]) = outv;
    if (lane == 0) g_valid[set][pid] = valid;
}

// ---------------------------------------------------------------------------
// B: fused line_scores.  block = 8x8 line pairs (80x80 C tile), 64 threads.
// A tile row-major [row][k] (float4 stores, conflict-free).
// B tile [k][col] transposed, stride 82 (<=4-way store conflicts vs 16-way).
// Accumulation order over k identical to the validated version.
// ---------------------------------------------------------------------------
__global__ __launch_bounds__(64)
void k_linescore() {
    __shared__ __align__(16) float As[80 * ASTRIDE];   // 21.8 KB
    __shared__ __align__(16) float Bs[64 * BSTRIDE];   // 21.0 KB
    __shared__ int v1s[80], v2s[80];

    int tid = threadIdx.x;
    int tx = tid & 7;          // j-line sub-index (B cols)
    int ty = tid >> 3;         // i-line sub-index (A rows)
    int rowA0 = blockIdx.y * 80;
    int rowB0 = blockIdx.x * 80;

    for (int i = tid; i < 80; i += 64) {
        v1s[i] = g_valid[0][rowA0 + i];
        v2s[i] = g_valid[1][rowB0 + i];
    }

    unsigned long long acc[10][5];
#pragma unroll
    for (int r = 0; r < 10; r++)
#pragma unroll
        for (int c = 0; c < 5; c++) acc[r][c] = 0ull;

    for (int kc = 0; kc < 128; kc += 64) {
#pragma unroll
        for (int l = 0; l < 20; l++) {
            int idx = tid + (l << 6);          // 0..1279
            int row = idx >> 4;
            int q   = idx & 15;
            float4 va = *reinterpret_cast<const float4*>(
                &g_dsc[0][(size_t)(rowA0 + row) * 128 + kc + q * 4]);
            float4 vb = *reinterpret_cast<const float4*>(
                &g_dsc[1][(size_t)(rowB0 + row) * 128 + kc + q * 4]);
            // A: row-major float4 store, conflict-free, 16B-aligned (272B rows)
            *reinterpret_cast<float4*>(&As[row * ASTRIDE + q * 4]) = va;
            // B: transposed scalar stores, stride 82 (<=4-way)
            int kb = q * 4;
            Bs[(kb + 0) * BSTRIDE + row] = vb.x;
            Bs[(kb + 1) * BSTRIDE + row] = vb.y;
            Bs[(kb + 2) * BSTRIDE + row] = vb.z;
            Bs[(kb + 3) * BSTRIDE + row] = vb.w;
        }
        __syncthreads();

#pragma unroll 8
        for (int kk = 0; kk < 64; kk++) {
            const unsigned long long* bp =
                reinterpret_cast<const unsigned long long*>(&Bs[kk * BSTRIDE + tx * 10]);
            unsigned long long bv[5];
#pragma unroll
            for (int c = 0; c < 5; c++) bv[c] = bp[c];
            const float* ap = &As[(ty * 10) * ASTRIDE + kk];
#pragma unroll
            for (int r = 0; r < 10; r++) {
                unsigned long long a2 = pack2(ap[r * ASTRIDE]);
#pragma unroll
                for (int c = 0; c < 5; c++) ffma2(acc[r][c], a2, bv[c]);
            }
        }
        __syncthreads();
    }

    float sc[10][10];
#pragma unroll
    for (int r = 0; r < 10; r++)
#pragma unroll
        for (int c = 0; c < 5; c++)
            unpack2(acc[r][c], sc[r][2 * c], sc[r][2 * c + 1]);

    int vr[10], vc[10];
#pragma unroll
    for (int s = 0; s < 10; s++) { vr[s] = v1s[ty * 10 + s]; vc[s] = v2s[tx * 10 + s]; }
#pragma unroll
    for (int r = 0; r < 10; r++)
#pragma unroll
        for (int c = 0; c < 10; c++)
            if (!(vr[r] && vc[c])) sc[r][c] = -1.0f;

    float sum1 = 0.0f; int c1 = 0;
#pragma unroll
    for (int r = 0; r < 10; r++) {
        float m = sc[r][0];
#pragma unroll
        for (int c = 1; c < 10; c++) m = fmaxf(m, sc[r][c]);
        if (m != -1.0f) { sum1 = __fadd_rn(sum1, m); c1++; }
    }
    float sum2 = 0.0f; int c2 = 0;
#pragma unroll
    for (int c = 0; c < 10; c++) {
        float m = sc[0][c];
#pragma unroll
        for (int r = 1; r < 10; r++) m = fmaxf(m, sc[r][c]);
        if (m != -1.0f) { sum2 = __fadd_rn(sum2, m); c2++; }
    }
    float m1 = __fdiv_rn(sum1, (float)c1);
    float m2 = __fdiv_rn(sum2, (float)c2);
    int i_line = blockIdx.y * 8 + ty;
    int j_line = blockIdx.x * 8 + tx;
    g_ls[i_line * NLINES + j_line] = __fmul_rn(__fadd_rn(m1, m2), 0.5f);
}

// ---------------------------------------------------------------------------
// C: top-10, one WARP per (dir,row).  16 values/lane in registers,
// 10x (local argmax + 5-step shfl_xor), tie -> larger index (stable argsort).
// ---------------------------------------------------------------------------
__global__ void k_topk() {
    int gw = blockIdx.x * 4 + (threadIdx.x >> 5);   // 0..1023
    int lane = threadIdx.x & 31;
    int dir = gw >> 9;
    int i   = gw & 511;

    float v[16]; int vi[16];
    if (dir == 0) {
        const float4* rp = reinterpret_cast<const float4*>(&g_ls[i * NLINES]);
#pragma unroll
        for (int m = 0; m < 4; m++) {
            float4 f = rp[m * 32 + lane];
            int base = 4 * (m * 32 + lane);
            v[4 * m + 0] = f.x; vi[4 * m + 0] = base + 0;
            v[4 * m + 1] = f.y; vi[4 * m + 1] = base + 1;
            v[4 * m + 2] = f.z; vi[4 * m + 2] = base + 2;
            v[4 * m + 3] = f.w; vi[4 * m + 3] = base + 3;
        }
    } else {
#pragma unroll
        for (int m = 0; m < 16; m++) {
            int r = m * 32 + lane;
            v[m] = g_ls[r * NLINES + i];
            vi[m] = r;
        }
    }

    for (int it = 0; it < 10; it++) {
        float bv = v[0]; int bi = vi[0];
#pragma unroll
        for (int m = 1; m < 16; m++)
            if (v[m] > bv || (v[m] == bv && vi[m] > bi)) { bv = v[m]; bi = vi[m]; }
#pragma unroll
        for (int o = 16; o > 0; o >>= 1) {
            float ov = __shfl_xor_sync(0xffffffffu, bv, o);
            int   oi = __shfl_xor_sync(0xffffffffu, bi, o);
            if (ov > bv || (ov == bv && oi > bi)) { bv = ov; bi = oi; }
        }
        if (lane == 0) g_topk[dir][i * 10 + (9 - it)] = bi;
#pragma unroll
        for (int m = 0; m < 16; m++)
            if (vi[m] == bi) v[m] = -3.0e38f;
    }
}

// ---------------------------------------------------------------------------
// D: per (dir, line): recompute candidate 10x10 blocks (float4 loads, same
// sequential-k summation order), run NW fwd+flip, argmax first-occurrence.
// ---------------------------------------------------------------------------
__global__ void k_match() {
    int blk = blockIdx.x;
    int dir = blk >> 9;
    int line = blk & 511;
    int qset = dir, cset = 1 - dir;
    int tid = threadIdx.x;    // 128 threads

    __shared__ __align__(16) float qd[SAMP * DCH];
    __shared__ int   qv[SAMP];
    __shared__ int   cands[10];
    __shared__ float sc[10 * 10 * 10]; // [cand][sq][s2]
    __shared__ float nw[20];

    {
        const float4* src = reinterpret_cast<const float4*>(
            &g_dsc[qset][(size_t)(line * SAMP) * DCH]);
        float4* dst = reinterpret_cast<float4*>(qd);
        for (int t = tid; t < SAMP * DCH / 4; t += 128) dst[t] = src[t];
    }
    if (tid < SAMP) qv[tid] = g_valid[qset][line * SAMP + tid];
    if (tid < 10)  cands[tid] = g_topk[dir][line * 10 + tid];
    __syncthreads();

    for (int idx = tid; idx < 1000; idx += 128) {
        int c   = idx / 100;
        int rem = idx - c * 100;
        int sq  = rem / 10;
        int s2  = rem - sq * 10;
        int cand = cands[c];
        const float4* cd = reinterpret_cast<const float4*>(
            &g_dsc[cset][(size_t)(cand * SAMP + s2) * DCH]);
        const float4* qp = reinterpret_cast<const float4*>(&qd[sq * DCH]);
        float sum = 0.0f;
#pragma unroll 8
        for (int k4 = 0; k4 < DCH / 4; k4++) {
            float4 a = qp[k4], b = cd[k4];
            sum = __fmaf_rn(a.x, b.x, sum);
            sum = __fmaf_rn(a.y, b.y, sum);
            sum = __fmaf_rn(a.z, b.z, sum);
            sum = __fmaf_rn(a.w, b.w, sum);
        }
        int cvalid = g_valid[cset][cand * SAMP + s2];
        sc[idx] = (qv[sq] && cvalid) ? sum : -1.0f;
    }
    __syncthreads();

    if (tid < 20) {
        int c = tid % 10;
        int flip = tid / 10;
        float prev[11];
#pragma unroll
        for (int j = 0; j < 11; j++) prev[j] = 0.0f;
#pragma unroll
        for (int r = 0; r < 10; r++) {
            float diag = prev[0];
            float run = -3.0e38f;
#pragma unroll
            for (int cc = 0; cc < 10; cc++) {
                int col = flip ? (9 - cc) : cc;
                float sval = __fsub_rn(sc[c * 100 + r * 10 + col], 0.1f);
                float oldn = prev[cc + 1];
                float a = fmaxf(oldn, __fadd_rn(diag, sval));
                run = fmaxf(run, a);
                prev[cc + 1] = fmaxf(run, 0.0f);
                diag = oldn;
            }
        }
        nw[tid] = prev[10];
    }
    __syncthreads();
    if (tid == 0) {
        int best = 0; float bv = nw[0];
        for (int j = 1; j < 20; j++)
            if (nw[j] > bv) { bv = nw[j]; best = j; }
        g_match[dir][line] = cands[best % 10];
    }
}

// ---------------------------------------------------------------------------
// E: mutual consistency -> FLOAT32 output
// ---------------------------------------------------------------------------
__global__ void k_mutual(float* __restrict__ out) {
    int i = threadIdx.x;
    int m = g_match[0][i];
    out[i] = (g_match[1][m] == i) ? (float)m : -1.0f;
}

// ---------------------------------------------------------------------------
extern "C" void kernel_launch(void* const* d_in, const int* in_sizes, int n_in,
                              void* d_out, int out_size) {
    const float* seg1  = (const float*)d_in[0];
    const float* seg2  = (const float*)d_in[1];
    const float* desc1 = (const float*)d_in[2];
    const float* desc2 = (const float*)d_in[3];
    float* out = (float*)d_out;

    k_transpose<<<dim3(512, 4, 2), dim3(32, 8)>>>(desc1, desc2);
    k_sample<<<1280, 256>>>(seg1, seg2);        // 8 warps/block, warp per point
    k_linescore<<<dim3(64, 64), 64>>>();
    k_topk<<<256, 128>>>();                     // warp per (dir,row)
    k_match<<<1024, 128>>>();
    k_mutual<<<1, 512>>>(out);
}

// round 13
// speedup vs baseline: 1.4752x; 1.0002x over previous
#include <cuda_runtime.h>
#include <cstdint>

// ---------------------------------------------------------------------------
// WunschLineMatcher — full pipeline on GB300 (sm_103a)
//
//  T) transpose desc [c][y][x] -> [y][x][c]
//  A) sample line points + bilinear + L2-normalize (warp per point)
//  B) fused 5120x5120x128 fp32 GEMM (fma.rn.f32x2) + per-pair-block (10x10)
//     masked max/mean epilogue -> line_scores[512][512].
//     A tile row-major (conflict-free), B tile transposed w/ padded stride.
//  C) top-10 per row/col: warp-per-row register top-k (argsort-stable ties)
//  D) NW on recomputed 10x10 candidate blocks (fwd + flipped), argmax
//  E) mutual check -> float32 output (-1 as int bit-pattern would be NaN)
// ---------------------------------------------------------------------------

#define NLINES 512
#define SAMP   10
#define DCH    128
#define HC     128
#define WC     128
#define NPTS   (NLINES * SAMP)   // 5120

#define ASTRIDE 68   // A tile row stride in floats (64 k + 4 pad) -> 272B, 16B-aligned
#define BSTRIDE 82   // B tile k-slice stride in floats (80 cols + 2 pad), even for LDS64

__device__ __align__(16) float g_dT[2][HC * WC * DCH];  // [set][(y*128+x)*128+c]
__device__ __align__(16) float g_dsc[2][NPTS * DCH];    // [set][point*128 + k]
__device__ int   g_valid[2][NPTS];
__device__ float g_ls[NLINES * NLINES];       // line_scores[i_set0][j_set1]
__device__ int   g_topk[2][NLINES * 10];      // ascending (slot 9 = best)
__device__ int   g_match[2][NLINES];

// ---------------------------------------------------------------------------
__device__ __forceinline__ void ffma2(unsigned long long& d,
                                      unsigned long long a,
                                      unsigned long long b) {
    asm("fma.rn.f32x2 %0, %1, %2, %0;" : "+l"(d) : "l"(a), "l"(b));
}
__device__ __forceinline__ unsigned long long pack2(float x) {
    unsigned long long r;
    asm("mov.b64 %0, {%1, %1};" : "=l"(r) : "f"(x));
    return r;
}
__device__ __forceinline__ void unpack2(unsigned long long v, float& lo, float& hi) {
    asm("mov.b64 {%0, %1}, %2;" : "=f"(lo), "=f"(hi) : "l"(v));
}

// ---------------------------------------------------------------------------
// T: transpose [c][y*x] (128 x 16384) -> [y*x][c]
// ---------------------------------------------------------------------------
__global__ void k_transpose(const float* __restrict__ d0,
                            const float* __restrict__ d1) {
    const float* src = blockIdx.z ? d1 : d0;
    float* dst = g_dT[blockIdx.z];
    __shared__ float tile[32][33];
    int p0 = blockIdx.x * 32;
    int c0 = blockIdx.y * 32;
    int tx = threadIdx.x, ty = threadIdx.y;
#pragma unroll
    for (int i = 0; i < 4; i++)
        tile[ty + 8 * i][tx] = src[(size_t)(c0 + ty + 8 * i) * 16384 + p0 + tx];
    __syncthreads();
#pragma unroll
    for (int i = 0; i < 4; i++)
        dst[(size_t)(p0 + ty + 8 * i) * 128 + c0 + tx] = tile[tx][ty + 8 * i];
}

// ---------------------------------------------------------------------------
// A: sample + bilinear + normalize.  one WARP per point (no block syncs).
// fp32 op-by-op identical to reference for the coordinate math.
// ---------------------------------------------------------------------------
__global__ void k_sample(const float* __restrict__ seg0,
                         const float* __restrict__ seg1) {
    int warp = blockIdx.x * (blockDim.x >> 5) + (threadIdx.x >> 5);  // 0..10239
    int lane = threadIdx.x & 31;
    int set = (warp >= NPTS) ? 1 : 0;
    int pid = warp - set * NPTS;
    int line = pid / SAMP;
    int t    = pid - line * SAMP;
    const float* seg = set ? seg1 : seg0;
    const float* dT  = g_dT[set];

    float a0 = seg[line * 4 + 0], a1 = seg[line * 4 + 1];
    float b0 = seg[line * 4 + 2], b1 = seg[line * 4 + 3];
    float e0 = __fsub_rn(a0, b0), e1 = __fsub_rn(a1, b1);
    float len = __fsqrt_rn(__fadd_rn(__fmul_rn(e0, e0), __fmul_rn(e1, e1)));
    float ns  = fminf(fmaxf(floorf(__fmul_rn(len, 0.125f)), 2.0f), 10.0f);
    float tf  = (float)t;
    int valid = (tf < ns) ? 1 : 0;
    float iv0 = __fdiv_rn(__fsub_rn(b0, a0), __fsub_rn(ns, 1.0f));
    float iv1 = __fdiv_rn(__fsub_rn(b1, a1), __fsub_rn(ns, 1.0f));
    float py  = __fadd_rn(a0, __fmul_rn(tf, iv0));
    float px  = __fadd_rn(a1, __fmul_rn(tf, iv1));
    if (!valid) { py = 0.0f; px = 0.0f; }

    float gx = __fsub_rn(__fdiv_rn(__fmul_rn(2.0f, px), 511.0f), 1.0f);
    float gy = __fsub_rn(__fdiv_rn(__fmul_rn(2.0f, py), 511.0f), 1.0f);
    float ix = __fmul_rn(__fsub_rn(__fmul_rn(__fadd_rn(gx, 1.0f), 128.0f), 1.0f), 0.5f);
    float iy = __fmul_rn(__fsub_rn(__fmul_rn(__fadd_rn(gy, 1.0f), 128.0f), 1.0f), 0.5f);
    float x0f = floorf(ix), y0f = floorf(iy);
    float wx = __fsub_rn(ix, x0f), wy = __fsub_rn(iy, y0f);
    float owx = __fsub_rn(1.0f, wx), owy = __fsub_rn(1.0f, wy);
    int x0 = (int)x0f, y0 = (int)y0f;

    int c4 = lane * 4;
    auto G4 = [&](int yy, int xx) -> float4 {
        bool inb = (xx >= 0) & (xx < WC) & (yy >= 0) & (yy < HC);
        int yc = min(max(yy, 0), HC - 1);
        int xc = min(max(xx, 0), WC - 1);
        float4 v = *reinterpret_cast<const float4*>(
            &dT[(size_t)(yc * WC + xc) * DCH + c4]);
        if (!inb) { v.x = 0.f; v.y = 0.f; v.z = 0.f; v.w = 0.f; }
        return v;
    };
    float4 p00 = G4(y0, x0), p01 = G4(y0, x0 + 1);
    float4 p10 = G4(y0 + 1, x0), p11 = G4(y0 + 1, x0 + 1);

    auto bil = [&](float g1, float g2, float g3, float g4) -> float {
        float t1 = __fmul_rn(__fmul_rn(g1, owy), owx);
        float t2 = __fmul_rn(__fmul_rn(g2, owy), wx);
        float t3 = __fmul_rn(__fmul_rn(g3, wy), owx);
        float t4 = __fmul_rn(__fmul_rn(g4, wy), wx);
        return __fadd_rn(__fadd_rn(__fadd_rn(t1, t2), t3), t4);
    };
    float v0 = bil(p00.x, p01.x, p10.x, p11.x);
    float v1 = bil(p00.y, p01.y, p10.y, p11.y);
    float v2 = bil(p00.z, p01.z, p10.z, p11.z);
    float v3 = bil(p00.w, p01.w, p10.w, p11.w);

    float sq = __fadd_rn(__fadd_rn(__fadd_rn(__fmul_rn(v0, v0), __fmul_rn(v1, v1)),
                                   __fmul_rn(v2, v2)), __fmul_rn(v3, v3));
#pragma unroll
    for (int o = 16; o > 0; o >>= 1)
        sq = __fadd_rn(sq, __shfl_xor_sync(0xffffffffu, sq, o));
    float nrm = fmaxf(__fsqrt_rn(sq), 1e-12f);

    float4 outv;
    outv.x = __fdiv_rn(v0, nrm);
    outv.y = __fdiv_rn(v1, nrm);
    outv.z = __fdiv_rn(v2, nrm);
    outv.w = __fdiv_rn(v3, nrm);
    *reinterpret_cast<float4*>(&g_dsc[set][(size_t)pid * DCH + c4]) = outv;
    if (lane == 0) g_valid[set][pid] = valid;
}

// ---------------------------------------------------------------------------
// B: fused line_scores.  block = 8x8 line pairs (80x80 C tile), 64 threads.
// A tile row-major [row][k] (float4 stores, conflict-free).
// B tile [k][col] transposed, stride 82 (<=4-way store conflicts vs 16-way).
// Accumulation order over k identical to the validated version.
// ---------------------------------------------------------------------------
__global__ __launch_bounds__(64)
void k_linescore() {
    __shared__ __align__(16) float As[80 * ASTRIDE];   // 21.8 KB
    __shared__ __align__(16) float Bs[64 * BSTRIDE];   // 21.0 KB
    __shared__ int v1s[80], v2s[80];

    int tid = threadIdx.x;
    int tx = tid & 7;          // j-line sub-index (B cols)
    int ty = tid >> 3;         // i-line sub-index (A rows)
    int rowA0 = blockIdx.y * 80;
    int rowB0 = blockIdx.x * 80;

    for (int i = tid; i < 80; i += 64) {
        v1s[i] = g_valid[0][rowA0 + i];
        v2s[i] = g_valid[1][rowB0 + i];
    }

    unsigned long long acc[10][5];
#pragma unroll
    for (int r = 0; r < 10; r++)
#pragma unroll
        for (int c = 0; c < 5; c++) acc[r][c] = 0ull;

    for (int kc = 0; kc < 128; kc += 64) {
#pragma unroll
        for (int l = 0; l < 20; l++) {
            int idx = tid + (l << 6);          // 0..1279
            int row = idx >> 4;
            int q   = idx & 15;
            float4 va = *reinterpret_cast<const float4*>(
                &g_dsc[0][(size_t)(rowA0 + row) * 128 + kc + q * 4]);
            float4 vb = *reinterpret_cast<const float4*>(
                &g_dsc[1][(size_t)(rowB0 + row) * 128 + kc + q * 4]);
            // A: row-major float4 store, conflict-free, 16B-aligned (272B rows)
            *reinterpret_cast<float4*>(&As[row * ASTRIDE + q * 4]) = va;
            // B: transposed scalar stores, stride 82 (<=4-way)
            int kb = q * 4;
            Bs[(kb + 0) * BSTRIDE + row] = vb.x;
            Bs[(kb + 1) * BSTRIDE + row] = vb.y;
            Bs[(kb + 2) * BSTRIDE + row] = vb.z;
            Bs[(kb + 3) * BSTRIDE + row] = vb.w;
        }
        __syncthreads();

#pragma unroll 8
        for (int kk = 0; kk < 64; kk++) {
            const unsigned long long* bp =
                reinterpret_cast<const unsigned long long*>(&Bs[kk * BSTRIDE + tx * 10]);
            unsigned long long bv[5];
#pragma unroll
            for (int c = 0; c < 5; c++) bv[c] = bp[c];
            const float* ap = &As[(ty * 10) * ASTRIDE + kk];
#pragma unroll
            for (int r = 0; r < 10; r++) {
                unsigned long long a2 = pack2(ap[r * ASTRIDE]);
#pragma unroll
                for (int c = 0; c < 5; c++) ffma2(acc[r][c], a2, bv[c]);
            }
        }
        __syncthreads();
    }

    float sc[10][10];
#pragma unroll
    for (int r = 0; r < 10; r++)
#pragma unroll
        for (int c = 0; c < 5; c++)
            unpack2(acc[r][c], sc[r][2 * c], sc[r][2 * c + 1]);

    int vr[10], vc[10];
#pragma unroll
    for (int s = 0; s < 10; s++) { vr[s] = v1s[ty * 10 + s]; vc[s] = v2s[tx * 10 + s]; }
#pragma unroll
    for (int r = 0; r < 10; r++)
#pragma unroll
        for (int c = 0; c < 10; c++)
            if (!(vr[r] && vc[c])) sc[r][c] = -1.0f;

    float sum1 = 0.0f; int c1 = 0;
#pragma unroll
    for (int r = 0; r < 10; r++) {
        float m = sc[r][0];
#pragma unroll
        for (int c = 1; c < 10; c++) m = fmaxf(m, sc[r][c]);
        if (m != -1.0f) { sum1 = __fadd_rn(sum1, m); c1++; }
    }
    float sum2 = 0.0f; int c2 = 0;
#pragma unroll
    for (int c = 0; c < 10; c++) {
        float m = sc[0][c];
#pragma unroll
        for (int r = 1; r < 10; r++) m = fmaxf(m, sc[r][c]);
        if (m != -1.0f) { sum2 = __fadd_rn(sum2, m); c2++; }
    }
    float m1 = __fdiv_rn(sum1, (float)c1);
    float m2 = __fdiv_rn(sum2, (float)c2);
    int i_line = blockIdx.y * 8 + ty;
    int j_line = blockIdx.x * 8 + tx;
    g_ls[i_line * NLINES + j_line] = __fmul_rn(__fadd_rn(m1, m2), 0.5f);
}

// ---------------------------------------------------------------------------
// C: top-10, one WARP per (dir,row).  16 values/lane in registers,
// 10x (local argmax + 5-step shfl_xor), tie -> larger index (stable argsort).
// ---------------------------------------------------------------------------
__global__ void k_topk() {
    int gw = blockIdx.x * 4 + (threadIdx.x >> 5);   // 0..1023
    int lane = threadIdx.x & 31;
    int dir = gw >> 9;
    int i   = gw & 511;

    float v[16]; int vi[16];
    if (dir == 0) {
        const float4* rp = reinterpret_cast<const float4*>(&g_ls[i * NLINES]);
#pragma unroll
        for (int m = 0; m < 4; m++) {
            float4 f = rp[m * 32 + lane];
            int base = 4 * (m * 32 + lane);
            v[4 * m + 0] = f.x; vi[4 * m + 0] = base + 0;
            v[4 * m + 1] = f.y; vi[4 * m + 1] = base + 1;
            v[4 * m + 2] = f.z; vi[4 * m + 2] = base + 2;
            v[4 * m + 3] = f.w; vi[4 * m + 3] = base + 3;
        }
    } else {
#pragma unroll
        for (int m = 0; m < 16; m++) {
            int r = m * 32 + lane;
            v[m] = g_ls[r * NLINES + i];
            vi[m] = r;
        }
    }

    for (int it = 0; it < 10; it++) {
        float bv = v[0]; int bi = vi[0];
#pragma unroll
        for (int m = 1; m < 16; m++)
            if (v[m] > bv || (v[m] == bv && vi[m] > bi)) { bv = v[m]; bi = vi[m]; }
#pragma unroll
        for (int o = 16; o > 0; o >>= 1) {
            float ov = __shfl_xor_sync(0xffffffffu, bv, o);
            int   oi = __shfl_xor_sync(0xffffffffu, bi, o);
            if (ov > bv || (ov == bv && oi > bi)) { bv = ov; bi = oi; }
        }
        if (lane == 0) g_topk[dir][i * 10 + (9 - it)] = bi;
#pragma unroll
        for (int m = 0; m < 16; m++)
            if (vi[m] == bi) v[m] = -3.0e38f;
    }
}

// ---------------------------------------------------------------------------
// D: per (dir, line): recompute candidate 10x10 blocks (float4 loads, same
// sequential-k summation order), run NW fwd+flip, argmax first-occurrence.
// ---------------------------------------------------------------------------
__global__ void k_match() {
    int blk = blockIdx.x;
    int dir = blk >> 9;
    int line = blk & 511;
    int qset = dir, cset = 1 - dir;
    int tid = threadIdx.x;    // 128 threads

    __shared__ __align__(16) float qd[SAMP * DCH];
    __shared__ int   qv[SAMP];
    __shared__ int   cands[10];
    __shared__ float sc[10 * 10 * 10]; // [cand][sq][s2]
    __shared__ float nw[20];

    {
        const float4* src = reinterpret_cast<const float4*>(
            &g_dsc[qset][(size_t)(line * SAMP) * DCH]);
        float4* dst = reinterpret_cast<float4*>(qd);
        for (int t = tid; t < SAMP * DCH / 4; t += 128) dst[t] = src[t];
    }
    if (tid < SAMP) qv[tid] = g_valid[qset][line * SAMP + tid];
    if (tid < 10)  cands[tid] = g_topk[dir][line * 10 + tid];
    __syncthreads();

    for (int idx = tid; idx < 1000; idx += 128) {
        int c   = idx / 100;
        int rem = idx - c * 100;
        int sq  = rem / 10;
        int s2  = rem - sq * 10;
        int cand = cands[c];
        const float4* cd = reinterpret_cast<const float4*>(
            &g_dsc[cset][(size_t)(cand * SAMP + s2) * DCH]);
        const float4* qp = reinterpret_cast<const float4*>(&qd[sq * DCH]);
        float sum = 0.0f;
#pragma unroll 8
        for (int k4 = 0; k4 < DCH / 4; k4++) {
            float4 a = qp[k4], b = cd[k4];
            sum = __fmaf_rn(a.x, b.x, sum);
            sum = __fmaf_rn(a.y, b.y, sum);
            sum = __fmaf_rn(a.z, b.z, sum);
            sum = __fmaf_rn(a.w, b.w, sum);
        }
        int cvalid = g_valid[cset][cand * SAMP + s2];
        sc[idx] = (qv[sq] && cvalid) ? sum : -1.0f;
    }
    __syncthreads();

    if (tid < 20) {
        int c = tid % 10;
        int flip = tid / 10;
        float prev[11];
#pragma unroll
        for (int j = 0; j < 11; j++) prev[j] = 0.0f;
#pragma unroll
        for (int r = 0; r < 10; r++) {
            float diag = prev[0];
            float run = -3.0e38f;
#pragma unroll
            for (int cc = 0; cc < 10; cc++) {
                int col = flip ? (9 - cc) : cc;
                float sval = __fsub_rn(sc[c * 100 + r * 10 + col], 0.1f);
                float oldn = prev[cc + 1];
                float a = fmaxf(oldn, __fadd_rn(diag, sval));
                run = fmaxf(run, a);
                prev[cc + 1] = fmaxf(run, 0.0f);
                diag = oldn;
            }
        }
        nw[tid] = prev[10];
    }
    __syncthreads();
    if (tid == 0) {
        int best = 0; float bv = nw[0];
        for (int j = 1; j < 20; j++)
            if (nw[j] > bv) { bv = nw[j]; best = j; }
        g_match[dir][line] = cands[best % 10];
    }
}

// ---------------------------------------------------------------------------
// E: mutual consistency -> FLOAT32 output
// ---------------------------------------------------------------------------
__global__ void k_mutual(float* __restrict__ out) {
    int i = threadIdx.x;
    int m = g_match[0][i];
    out[i] = (g_match[1][m] == i) ? (float)m : -1.0f;
}

// ---------------------------------------------------------------------------
extern "C" void kernel_launch(void* const* d_in, const int* in_sizes, int n_in,
                              void* d_out, int out_size) {
    const float* seg1  = (const float*)d_in[0];
    const float* seg2  = (const float*)d_in[1];
    const float* desc1 = (const float*)d_in[2];
    const float* desc2 = (const float*)d_in[3];
    float* out = (float*)d_out;

    k_transpose<<<dim3(512, 4, 2), dim3(32, 8)>>>(desc1, desc2);
    k_sample<<<1280, 256>>>(seg1, seg2);        // 8 warps/block, warp per point
    k_linescore<<<dim3(64, 64), 64>>>();
    k_topk<<<256, 128>>>();                     // warp per (dir,row)
    k_match<<<1024, 128>>>();
    k_mutual<<<1, 512>>>(out);
}